// round 5
// baseline (speedup 1.0000x reference)
#include <cuda_runtime.h>
#include <cuda_fp16.h>

#define BB    8
#define SS    4096
#define HH    2048
#define DHH   64
#define KSEL  256

typedef unsigned long long ull;

// scratch (no cudaMalloc allowed)
__device__ float d_logits[BB * SS];
__device__ int   d_sel[BB * KSEL];

__device__ __forceinline__ void fma2(ull& c, ull a, ull b) {
    asm("fma.rn.f32x2 %0, %1, %2, %0;" : "+l"(c) : "l"(a), "l"(b));
}
__device__ __forceinline__ ull mk64(unsigned lo, unsigned hi) {
    ull r; asm("mov.b64 %0, {%1, %2};" : "=l"(r) : "r"(lo), "r"(hi)); return r;
}
// fp32 rounded through fp16 (reference does .astype(float16); harness compares fp32)
__device__ __forceinline__ float h16(float v) {
    return __half2float(__float2half_rn(v));
}

// ============================================================================
// Kernel 1: fused logits GEMM (fp32 via packed f32x2 FMA), double-buffered
// software pipeline, + fp16-rounded fp32 copy of hidden_states into out.
// C[32768,64] = hs·w1 ; logit = relu(C+b1)·w2 + b2
// BM=64 tokens, BK=16, 256 threads. Thread (tx=tid&7, ty=tid>>3) owns
// tokens {ty, ty+32} x cols [tx*8, tx*8+8) as 2x4 packed f32x2 accumulators.
// ============================================================================
constexpr int BM = 64, BK = 16, NCHUNK = HH / BK;

__global__ __launch_bounds__(256, 4)
void k_gemm(const float* __restrict__ hs, const float* __restrict__ w1,
            const float* __restrict__ b1, const float* __restrict__ w2,
            const float* __restrict__ b2, float* __restrict__ out)
{
    __shared__ float2 a_s[2][BM][BK + 1];   // duplicated (a,a), pad vs conflicts
    __shared__ float  b_s[2][BK][DHH];

    const int tid  = threadIdx.x;
    const int tx   = tid & 7;
    const int ty   = tid >> 3;              // 0..31
    const int tok0 = blockIdx.x * BM;

    // A-stage mapping: 64 rows x 16 floats, 4 threads per row (float4 each)
    const int ar = tid >> 2;                // 0..63
    const int ak = (tid & 3) * 4;           // 0,4,8,12
    // B-stage mapping: 16 rows x 64 floats, 16 threads per row
    const int br = tid >> 4;                // 0..15
    const int bc = (tid & 15) * 4;

    const float* hsA = hs  + (size_t)(tok0 + ar) * HH + ak;
    float*       oA  = out + (size_t)(tok0 + ar) * HH + ak;

    ull acc[2][4];
#pragma unroll
    for (int t = 0; t < 2; t++)
#pragma unroll
        for (int i = 0; i < 4; i++) acc[t][i] = 0ull;

    // prologue prefetch
    float4 va = *reinterpret_cast<const float4*>(hsA);
    float4 vb = *reinterpret_cast<const float4*>(w1 + (size_t)br * DHH + bc);

    for (int c = 0; c < NCHUNK; c++) {
        const int buf = c & 1;
        // stage prefetched regs -> smem ; emit fp16-rounded output copy
        a_s[buf][ar][ak + 0] = make_float2(va.x, va.x);
        a_s[buf][ar][ak + 1] = make_float2(va.y, va.y);
        a_s[buf][ar][ak + 2] = make_float2(va.z, va.z);
        a_s[buf][ar][ak + 3] = make_float2(va.w, va.w);
        *reinterpret_cast<float4*>(&b_s[buf][br][bc]) = vb;
        float4 ov = make_float4(h16(va.x), h16(va.y), h16(va.z), h16(va.w));
        *reinterpret_cast<float4*>(oA + (size_t)c * BK) = ov;
        __syncthreads();

        // prefetch next chunk (overlaps with compute below)
        if (c + 1 < NCHUNK) {
            va = *reinterpret_cast<const float4*>(hsA + (size_t)(c + 1) * BK);
            vb = *reinterpret_cast<const float4*>(
                     w1 + (size_t)((c + 1) * BK + br) * DHH + bc);
        }

        // compute chunk from smem[buf]
#pragma unroll
        for (int kk = 0; kk < BK; kk++) {
            const uint4 u0 = *reinterpret_cast<const uint4*>(&b_s[buf][kk][tx * 8]);
            const uint4 u1 = *reinterpret_cast<const uint4*>(&b_s[buf][kk][tx * 8 + 4]);
            ull bv0 = mk64(u0.x, u0.y), bv1 = mk64(u0.z, u0.w);
            ull bv2 = mk64(u1.x, u1.y), bv3 = mk64(u1.z, u1.w);
            ull av0 = *reinterpret_cast<const ull*>(&a_s[buf][ty][kk]);
            ull av1 = *reinterpret_cast<const ull*>(&a_s[buf][ty + 32][kk]);
            fma2(acc[0][0], av0, bv0); fma2(acc[0][1], av0, bv1);
            fma2(acc[0][2], av0, bv2); fma2(acc[0][3], av0, bv3);
            fma2(acc[1][0], av1, bv0); fma2(acc[1][1], av1, bv1);
            fma2(acc[1][2], av1, bv2); fma2(acc[1][3], av1, bv3);
        }
        __syncthreads();
    }

    // epilogue: +b1, relu, dot w2, reduce over 8 tx lanes
    const float4 b1a = *reinterpret_cast<const float4*>(b1 + tx * 8);
    const float4 b1b = *reinterpret_cast<const float4*>(b1 + tx * 8 + 4);
    const float4 w2a = *reinterpret_cast<const float4*>(w2 + tx * 8);
    const float4 w2b = *reinterpret_cast<const float4*>(w2 + tx * 8 + 4);
    const float b2v = b2[0];
    const float b1v[8] = {b1a.x, b1a.y, b1a.z, b1a.w, b1b.x, b1b.y, b1b.z, b1b.w};
    const float w2v[8] = {w2a.x, w2a.y, w2a.z, w2a.w, w2b.x, w2b.y, w2b.z, w2b.w};

#pragma unroll
    for (int t = 0; t < 2; t++) {
        float p = 0.f;
#pragma unroll
        for (int i = 0; i < 4; i++) {
            float lo = __uint_as_float((unsigned)(acc[t][i] & 0xffffffffull));
            float hi = __uint_as_float((unsigned)(acc[t][i] >> 32));
            p += fmaxf(lo + b1v[2 * i],     0.f) * w2v[2 * i]
               + fmaxf(hi + b1v[2 * i + 1], 0.f) * w2v[2 * i + 1];
        }
        p += __shfl_down_sync(0xffffffffu, p, 4, 8);
        p += __shfl_down_sync(0xffffffffu, p, 2, 8);
        p += __shfl_down_sync(0xffffffffu, p, 1, 8);
        if (tx == 0) d_logits[tok0 + ty + t * 32] = p + b2v;
    }
}

// ============================================================================
// Kernel 2: per-batch gumbel top-k (full bitonic sort, matches jax.lax.top_k
// descending order + stable lowest-index tiebreak) + logsumexp + log_prob.
// ============================================================================
__global__ __launch_bounds__(512)
void k_topk(const float* __restrict__ noise, float* __restrict__ out,
            int write_extras)
{
    const int b   = blockIdx.x;
    const int tid = threadIdx.x;
    __shared__ ull   keys[SS];
    __shared__ float red[512];

    const float* lg = d_logits + b * SS;
    const float* nu = noise    + b * SS;

    float m = -3.4e38f;
    for (int i = tid; i < SS; i += 512) {
        float l = lg[i];
        float s = l - logf(-logf(nu[i]));          // logit + gumbel
        unsigned u = __float_as_uint(s);
        u = (u & 0x80000000u) ? ~u : (u | 0x80000000u);
        keys[i] = ((ull)u << 32) | (unsigned)(~(unsigned)i);
        m = fmaxf(m, l);
    }
    red[tid] = m; __syncthreads();
    for (int s2 = 256; s2 > 0; s2 >>= 1) {
        if (tid < s2) red[tid] = fmaxf(red[tid], red[tid + s2]);
        __syncthreads();
    }
    m = red[0]; __syncthreads();
    float sum = 0.f;
    for (int i = tid; i < SS; i += 512) sum += expf(lg[i] - m);
    red[tid] = sum; __syncthreads();
    for (int s2 = 256; s2 > 0; s2 >>= 1) {
        if (tid < s2) red[tid] += red[tid + s2];
        __syncthreads();
    }
    const float lse = m + logf(red[0]);
    __syncthreads();

    for (int size = 2; size <= SS; size <<= 1) {
        for (int stride = size >> 1; stride > 0; stride >>= 1) {
            for (int t = tid; t < SS / 2; t += 512) {
                int i = 2 * t - (t & (stride - 1));
                int j = i + stride;
                bool desc = ((i & size) == 0);
                ull a = keys[i], c = keys[j];
                bool sw = desc ? (a < c) : (a > c);
                if (sw) { keys[i] = c; keys[j] = a; }
            }
            __syncthreads();
        }
    }

    float lp = 0.f;
    for (int kk = tid; kk < KSEL; kk += 512) {
        int idx = (int)(~(unsigned)(keys[kk] & 0xffffffffull));
        d_sel[b * KSEL + kk] = idx;
        lp += lg[idx] - lse;
        if (write_extras) {
            out[(size_t)BB * SS * HH + b * KSEL + kk] = (float)idx;           // indices
            out[(size_t)BB * SS * HH + BB * KSEL + b * KSEL + kk] = 1.0f;     // types
        }
    }
    red[tid] = lp; __syncthreads();
    for (int s2 = 256; s2 > 0; s2 >>= 1) {
        if (tid < s2) red[tid] += red[tid + s2];
        __syncthreads();
    }
    if (tid == 0 && write_extras)
        out[(size_t)BB * SS * HH + 2 * BB * KSEL + b] = red[0] / (float)KSEL; // log_prob
}

// ============================================================================
// Kernel 3: zero selected rows (perturb value = TYPE_VALUES[1]*SCALE = 0.0)
// ============================================================================
__global__ __launch_bounds__(256)
void k_zero(float* __restrict__ out)
{
    const int b   = blockIdx.y;
    const int row = d_sel[b * KSEL + blockIdx.x];
    float4* p = reinterpret_cast<float4*>(out + ((size_t)b * SS + row) * HH);
    const float4 z = make_float4(0.f, 0.f, 0.f, 0.f);
    p[threadIdx.x]       = z;
    p[threadIdx.x + 256] = z;
}

// ============================================================================
extern "C" void kernel_launch(void* const* d_in, const int* in_sizes, int n_in,
                              void* d_out, int out_size)
{
    const float* hs = (const float*)d_in[0];   // (8,4096,2048) fp32
    const float* nu = (const float*)d_in[1];   // (8,4096)      fp32
    const float* w1 = (const float*)d_in[2];   // (2048,64)
    const float* b1 = (const float*)d_in[3];   // (64,)
    const float* w2 = (const float*)d_in[4];   // (64,1)
    const float* b2 = (const float*)d_in[5];   // (1,)
    float* out = (float*)d_out;

    const long long need = (long long)BB * SS * HH + 2LL * BB * KSEL + BB;
    const int write_extras = ((long long)out_size >= need) ? 1 : 0;

    k_gemm<<<(BB * SS) / BM, 256>>>(hs, w1, b1, w2, b2, out);
    k_topk<<<BB, 512>>>(nu, out, write_extras);
    k_zero<<<dim3(KSEL, BB), 256>>>(out);
    (void)in_sizes; (void)n_in;
}

// round 6
// speedup vs baseline: 1.6295x; 1.6295x over previous
#include <cuda_runtime.h>
#include <cuda_fp16.h>

#define BB    8
#define SS    4096
#define HH    2048
#define DHH   64
#define KSEL  256

typedef unsigned long long ull;

// scratch (no cudaMalloc allowed)
__device__ float d_logits[BB * SS];
__device__ int   d_sel[BB * KSEL];

__device__ __forceinline__ void fma2(ull& c, ull a, ull b) {
    asm("fma.rn.f32x2 %0, %1, %2, %0;" : "+l"(c) : "l"(a), "l"(b));
}
__device__ __forceinline__ ull mk64(unsigned lo, unsigned hi) {
    ull r; asm("mov.b64 %0, {%1, %2};" : "=l"(r) : "r"(lo), "r"(hi)); return r;
}
// fp32 rounded through fp16 (reference does .astype(float16); harness compares fp32)
__device__ __forceinline__ float h16(float v) {
    return __half2float(__float2half_rn(v));
}

// ============================================================================
// Kernel 1: fused logits GEMM (fp32 packed f32x2 FMA), double-buffered,
// single-sync pipeline + fp16-rounded fp32 copy of hidden_states into out.
// BM=128 tokens, BK=16, 256 threads. Thread (tx=tid&7, ty=tid>>3) owns
// tokens {ty, ty+32, ty+64, ty+96} x cols [tx*8, tx*8+8):
// per kk -> 4 LDS.64 (A) + 2 LDS.128 (B) feed 16 FFMA2 (fma-pipe bound).
// ============================================================================
constexpr int BM = 128, BK = 16, NCHUNK = HH / BK;

__global__ __launch_bounds__(256, 2)
void k_gemm(const float* __restrict__ hs, const float* __restrict__ w1,
            const float* __restrict__ b1, const float* __restrict__ w2,
            const float* __restrict__ b2, float* __restrict__ out)
{
    __shared__ float2 a_s[2][BM][BK + 1];   // (a,a) duplicated, padded stride
    __shared__ float  b_s[2][BK][DHH];

    const int tid  = threadIdx.x;
    const int tx   = tid & 7;
    const int ty   = tid >> 3;               // 0..31
    const int tok0 = blockIdx.x * BM;

    // A staging: 128 rows x 16 floats = 512 float4; thread t -> f={t, t+256}
    const int r0 = tid >> 2;                 // 0..63  (second row = r0+64)
    const int kc = (tid & 3) * 4;            // 0,4,8,12
    // B staging: 16 rows x 64 floats = 256 float4; one per thread
    const int br = tid >> 4;                 // 0..15
    const int bc = (tid & 15) * 4;

    const float* hs0 = hs  + (size_t)(tok0 + r0)      * HH + kc;
    const float* hs1 = hs  + (size_t)(tok0 + r0 + 64) * HH + kc;
    float*       o0  = out + (size_t)(tok0 + r0)      * HH + kc;
    float*       o1  = out + (size_t)(tok0 + r0 + 64) * HH + kc;

    ull acc[4][4];
#pragma unroll
    for (int t = 0; t < 4; t++)
#pragma unroll
        for (int i = 0; i < 4; i++) acc[t][i] = 0ull;

    // ---- prologue: chunk 0 ----
    float4 va0 = *reinterpret_cast<const float4*>(hs0);
    float4 va1 = *reinterpret_cast<const float4*>(hs1);
    float4 vb  = *reinterpret_cast<const float4*>(w1 + (size_t)br * DHH + bc);
    {
        a_s[0][r0][kc + 0] = make_float2(va0.x, va0.x);
        a_s[0][r0][kc + 1] = make_float2(va0.y, va0.y);
        a_s[0][r0][kc + 2] = make_float2(va0.z, va0.z);
        a_s[0][r0][kc + 3] = make_float2(va0.w, va0.w);
        a_s[0][r0 + 64][kc + 0] = make_float2(va1.x, va1.x);
        a_s[0][r0 + 64][kc + 1] = make_float2(va1.y, va1.y);
        a_s[0][r0 + 64][kc + 2] = make_float2(va1.z, va1.z);
        a_s[0][r0 + 64][kc + 3] = make_float2(va1.w, va1.w);
        *reinterpret_cast<float4*>(&b_s[0][br][bc]) = vb;
        *reinterpret_cast<float4*>(o0) =
            make_float4(h16(va0.x), h16(va0.y), h16(va0.z), h16(va0.w));
        *reinterpret_cast<float4*>(o1) =
            make_float4(h16(va1.x), h16(va1.y), h16(va1.z), h16(va1.w));
    }
    __syncthreads();

    for (int c = 0; c < NCHUNK; c++) {
        const int buf = c & 1;

        // prefetch chunk c+1 into registers (overlaps compute)
        if (c + 1 < NCHUNK) {
            va0 = *reinterpret_cast<const float4*>(hs0 + (size_t)(c + 1) * BK);
            va1 = *reinterpret_cast<const float4*>(hs1 + (size_t)(c + 1) * BK);
            vb  = *reinterpret_cast<const float4*>(
                      w1 + (size_t)((c + 1) * BK + br) * DHH + bc);
        }

        // compute chunk c from smem[buf]
#pragma unroll
        for (int kk = 0; kk < BK; kk++) {
            const uint4 u0 = *reinterpret_cast<const uint4*>(&b_s[buf][kk][tx * 8]);
            const uint4 u1 = *reinterpret_cast<const uint4*>(&b_s[buf][kk][tx * 8 + 4]);
            const ull bv0 = mk64(u0.x, u0.y), bv1 = mk64(u0.z, u0.w);
            const ull bv2 = mk64(u1.x, u1.y), bv3 = mk64(u1.z, u1.w);
#pragma unroll
            for (int t = 0; t < 4; t++) {
                const ull av = *reinterpret_cast<const ull*>(&a_s[buf][ty + 32 * t][kk]);
                fma2(acc[t][0], av, bv0);
                fma2(acc[t][1], av, bv1);
                fma2(acc[t][2], av, bv2);
                fma2(acc[t][3], av, bv3);
            }
        }

        // stage chunk c+1 into the other buffer; emit output copy
        if (c + 1 < NCHUNK) {
            const int nb = buf ^ 1;
            a_s[nb][r0][kc + 0] = make_float2(va0.x, va0.x);
            a_s[nb][r0][kc + 1] = make_float2(va0.y, va0.y);
            a_s[nb][r0][kc + 2] = make_float2(va0.z, va0.z);
            a_s[nb][r0][kc + 3] = make_float2(va0.w, va0.w);
            a_s[nb][r0 + 64][kc + 0] = make_float2(va1.x, va1.x);
            a_s[nb][r0 + 64][kc + 1] = make_float2(va1.y, va1.y);
            a_s[nb][r0 + 64][kc + 2] = make_float2(va1.z, va1.z);
            a_s[nb][r0 + 64][kc + 3] = make_float2(va1.w, va1.w);
            *reinterpret_cast<float4*>(&b_s[nb][br][bc]) = vb;
            *reinterpret_cast<float4*>(o0 + (size_t)(c + 1) * BK) =
                make_float4(h16(va0.x), h16(va0.y), h16(va0.z), h16(va0.w));
            *reinterpret_cast<float4*>(o1 + (size_t)(c + 1) * BK) =
                make_float4(h16(va1.x), h16(va1.y), h16(va1.z), h16(va1.w));
            __syncthreads();
        }
    }

    // epilogue: +b1, relu, dot w2, reduce over 8 tx lanes
    const float4 b1a = *reinterpret_cast<const float4*>(b1 + tx * 8);
    const float4 b1b = *reinterpret_cast<const float4*>(b1 + tx * 8 + 4);
    const float4 w2a = *reinterpret_cast<const float4*>(w2 + tx * 8);
    const float4 w2b = *reinterpret_cast<const float4*>(w2 + tx * 8 + 4);
    const float b2v = b2[0];
    const float b1v[8] = {b1a.x, b1a.y, b1a.z, b1a.w, b1b.x, b1b.y, b1b.z, b1b.w};
    const float w2v[8] = {w2a.x, w2a.y, w2a.z, w2a.w, w2b.x, w2b.y, w2b.z, w2b.w};

#pragma unroll
    for (int t = 0; t < 4; t++) {
        float p = 0.f;
#pragma unroll
        for (int i = 0; i < 4; i++) {
            float lo = __uint_as_float((unsigned)(acc[t][i] & 0xffffffffull));
            float hi = __uint_as_float((unsigned)(acc[t][i] >> 32));
            p += fmaxf(lo + b1v[2 * i],     0.f) * w2v[2 * i]
               + fmaxf(hi + b1v[2 * i + 1], 0.f) * w2v[2 * i + 1];
        }
        p += __shfl_down_sync(0xffffffffu, p, 4, 8);
        p += __shfl_down_sync(0xffffffffu, p, 2, 8);
        p += __shfl_down_sync(0xffffffffu, p, 1, 8);
        if (tx == 0) d_logits[tok0 + ty + 32 * t] = p + b2v;
    }
}

// ============================================================================
// Kernel 2: per-batch gumbel top-k (full bitonic sort, matches jax.lax.top_k
// descending order + stable lowest-index tiebreak) + logsumexp + log_prob.
// ============================================================================
__global__ __launch_bounds__(512)
void k_topk(const float* __restrict__ noise, float* __restrict__ out,
            int write_extras)
{
    const int b   = blockIdx.x;
    const int tid = threadIdx.x;
    __shared__ ull   keys[SS];
    __shared__ float red[512];

    const float* lg = d_logits + b * SS;
    const float* nu = noise    + b * SS;

    float m = -3.4e38f;
    for (int i = tid; i < SS; i += 512) {
        float l = lg[i];
        float s = l - logf(-logf(nu[i]));          // logit + gumbel
        unsigned u = __float_as_uint(s);
        u = (u & 0x80000000u) ? ~u : (u | 0x80000000u);
        keys[i] = ((ull)u << 32) | (unsigned)(~(unsigned)i);
        m = fmaxf(m, l);
    }
    red[tid] = m; __syncthreads();
    for (int s2 = 256; s2 > 0; s2 >>= 1) {
        if (tid < s2) red[tid] = fmaxf(red[tid], red[tid + s2]);
        __syncthreads();
    }
    m = red[0]; __syncthreads();
    float sum = 0.f;
    for (int i = tid; i < SS; i += 512) sum += expf(lg[i] - m);
    red[tid] = sum; __syncthreads();
    for (int s2 = 256; s2 > 0; s2 >>= 1) {
        if (tid < s2) red[tid] += red[tid + s2];
        __syncthreads();
    }
    const float lse = m + logf(red[0]);
    __syncthreads();

    for (int size = 2; size <= SS; size <<= 1) {
        for (int stride = size >> 1; stride > 0; stride >>= 1) {
            for (int t = tid; t < SS / 2; t += 512) {
                int i = 2 * t - (t & (stride - 1));
                int j = i + stride;
                bool desc = ((i & size) == 0);
                ull a = keys[i], c = keys[j];
                bool sw = desc ? (a < c) : (a > c);
                if (sw) { keys[i] = c; keys[j] = a; }
            }
            __syncthreads();
        }
    }

    float lp = 0.f;
    for (int kk = tid; kk < KSEL; kk += 512) {
        int idx = (int)(~(unsigned)(keys[kk] & 0xffffffffull));
        d_sel[b * KSEL + kk] = idx;
        lp += lg[idx] - lse;
        if (write_extras) {
            out[(size_t)BB * SS * HH + b * KSEL + kk] = (float)idx;           // indices
            out[(size_t)BB * SS * HH + BB * KSEL + b * KSEL + kk] = 1.0f;     // types
        }
    }
    red[tid] = lp; __syncthreads();
    for (int s2 = 256; s2 > 0; s2 >>= 1) {
        if (tid < s2) red[tid] += red[tid + s2];
        __syncthreads();
    }
    if (tid == 0 && write_extras)
        out[(size_t)BB * SS * HH + 2 * BB * KSEL + b] = red[0] / (float)KSEL; // log_prob
}

// ============================================================================
// Kernel 3: zero selected rows (perturb value = TYPE_VALUES[1]*SCALE = 0.0)
// ============================================================================
__global__ __launch_bounds__(256)
void k_zero(float* __restrict__ out)
{
    const int b   = blockIdx.y;
    const int row = d_sel[b * KSEL + blockIdx.x];
    float4* p = reinterpret_cast<float4*>(out + ((size_t)b * SS + row) * HH);
    const float4 z = make_float4(0.f, 0.f, 0.f, 0.f);
    p[threadIdx.x]       = z;
    p[threadIdx.x + 256] = z;
}

// ============================================================================
extern "C" void kernel_launch(void* const* d_in, const int* in_sizes, int n_in,
                              void* d_out, int out_size)
{
    const float* hs = (const float*)d_in[0];   // (8,4096,2048) fp32
    const float* nu = (const float*)d_in[1];   // (8,4096)      fp32
    const float* w1 = (const float*)d_in[2];   // (2048,64)
    const float* b1 = (const float*)d_in[3];   // (64,)
    const float* w2 = (const float*)d_in[4];   // (64,1)
    const float* b2 = (const float*)d_in[5];   // (1,)
    float* out = (float*)d_out;

    const long long need = (long long)BB * SS * HH + 2LL * BB * KSEL + BB;
    const int write_extras = ((long long)out_size >= need) ? 1 : 0;

    k_gemm<<<(BB * SS) / BM, 256>>>(hs, w1, b1, w2, b2, out);
    k_topk<<<BB, 512>>>(nu, out, write_extras);
    k_zero<<<dim3(KSEL, BB), 256>>>(out);
    (void)in_sizes; (void)n_in;
}

// round 7
// speedup vs baseline: 2.2795x; 1.3989x over previous
#include <cuda_runtime.h>
#include <cuda_fp16.h>

#define BB    8
#define SS    4096
#define HH    2048
#define DHH   64
#define KSEL  256

typedef unsigned long long ull;

// scratch (no cudaMalloc allowed)
__device__ float d_logits[BB * SS];
__device__ int   d_sel[BB * KSEL];

__device__ __forceinline__ void fma2(ull& c, ull a, ull b) {
    asm("fma.rn.f32x2 %0, %1, %2, %0;" : "+l"(c) : "l"(a), "l"(b));
}
__device__ __forceinline__ ull mk64(unsigned lo, unsigned hi) {
    ull r; asm("mov.b64 %0, {%1, %2};" : "=l"(r) : "r"(lo), "r"(hi)); return r;
}
// fp32 rounded through fp16 (reference does .astype(float16); harness compares fp32)
__device__ __forceinline__ float h16(float v) {
    return __half2float(__float2half_rn(v));
}

// ============================================================================
// Kernel 1: fused logits GEMM, deep register blocking (8 tok x 8 col / thread)
// to get LDS traffic under the FFMA2 roof. Double-buffered single-sync
// pipeline + fp16-rounded fp32 copy of hidden_states into out.
// Block = 128 threads (tx = tid&7 -> 8 cols, ty = tid>>3 -> 16 row-groups).
// Thread owns tokens {ty + 16t, t=0..7} x cols [tx*8, tx*8+8).
// Per kk per warp: 32 FFMA2 vs 10 LDS wavefronts.
// ============================================================================
constexpr int BM = 128, BK = 16, NCHUNK = HH / BK;

__global__ __launch_bounds__(128, 2)
void k_gemm(const float* __restrict__ hs, const float* __restrict__ w1,
            const float* __restrict__ b1, const float* __restrict__ w2,
            const float* __restrict__ b2, float* __restrict__ out)
{
    __shared__ float2 a_s[2][BM][BK + 1];   // (a,a) duplicated, padded: 34.8KB
    __shared__ float  b_s[2][BK][DHH];      // 8KB

    const int tid  = threadIdx.x;
    const int tx   = tid & 7;
    const int ty   = tid >> 3;               // 0..15
    const int tok0 = blockIdx.x * BM;

    // A staging: flat = i*128 + tid (i=0..3): row = 32*i + (tid>>2), kq=(tid&3)*4
    const int arow = tid >> 2;                // 0..31 (+32i)
    const int akq  = (tid & 3) * 4;           // 0,4,8,12
    // B staging: flat = j*128 + tid (j=0..1): brow = flat>>4, bcol=(flat&15)*4
    const int br0  = tid >> 4;                // 0..7 (j=0), +8 (j=1)
    const int bc   = (tid & 15) * 4;

    const float* hsA = hs  + (size_t)(tok0 + arow) * HH + akq;
    float*       oA  = out + (size_t)(tok0 + arow) * HH + akq;

    ull acc[8][4];
#pragma unroll
    for (int t = 0; t < 8; t++)
#pragma unroll
        for (int i = 0; i < 4; i++) acc[t][i] = 0ull;

    float4 va[4], vb[2];
    // ---- prologue: chunk 0 ----
#pragma unroll
    for (int i = 0; i < 4; i++)
        va[i] = *reinterpret_cast<const float4*>(hsA + (size_t)(32 * i) * HH);
#pragma unroll
    for (int j = 0; j < 2; j++)
        vb[j] = *reinterpret_cast<const float4*>(w1 + (size_t)(br0 + 8 * j) * DHH + bc);
#pragma unroll
    for (int i = 0; i < 4; i++) {
        a_s[0][32 * i + arow][akq + 0] = make_float2(va[i].x, va[i].x);
        a_s[0][32 * i + arow][akq + 1] = make_float2(va[i].y, va[i].y);
        a_s[0][32 * i + arow][akq + 2] = make_float2(va[i].z, va[i].z);
        a_s[0][32 * i + arow][akq + 3] = make_float2(va[i].w, va[i].w);
        *reinterpret_cast<float4*>(oA + (size_t)(32 * i) * HH) =
            make_float4(h16(va[i].x), h16(va[i].y), h16(va[i].z), h16(va[i].w));
    }
#pragma unroll
    for (int j = 0; j < 2; j++)
        *reinterpret_cast<float4*>(&b_s[0][br0 + 8 * j][bc]) = vb[j];
    __syncthreads();

    for (int c = 0; c < NCHUNK; c++) {
        const int buf = c & 1;

        // prefetch chunk c+1 into registers (overlaps compute below)
        if (c + 1 < NCHUNK) {
#pragma unroll
            for (int i = 0; i < 4; i++)
                va[i] = *reinterpret_cast<const float4*>(
                    hsA + (size_t)(32 * i) * HH + (size_t)(c + 1) * BK);
#pragma unroll
            for (int j = 0; j < 2; j++)
                vb[j] = *reinterpret_cast<const float4*>(
                    w1 + (size_t)((c + 1) * BK + br0 + 8 * j) * DHH + bc);
        }

        // compute chunk c from smem[buf]
#pragma unroll
        for (int kk = 0; kk < BK; kk++) {
            const uint4 u0 = *reinterpret_cast<const uint4*>(&b_s[buf][kk][tx * 8]);
            const uint4 u1 = *reinterpret_cast<const uint4*>(&b_s[buf][kk][tx * 8 + 4]);
            const ull bv0 = mk64(u0.x, u0.y), bv1 = mk64(u0.z, u0.w);
            const ull bv2 = mk64(u1.x, u1.y), bv3 = mk64(u1.z, u1.w);
#pragma unroll
            for (int t = 0; t < 8; t++) {
                const ull av = *reinterpret_cast<const ull*>(&a_s[buf][ty + 16 * t][kk]);
                fma2(acc[t][0], av, bv0);
                fma2(acc[t][1], av, bv1);
                fma2(acc[t][2], av, bv2);
                fma2(acc[t][3], av, bv3);
            }
        }

        // stage chunk c+1 into the other buffer; emit output copy
        if (c + 1 < NCHUNK) {
            const int nb = buf ^ 1;
#pragma unroll
            for (int i = 0; i < 4; i++) {
                a_s[nb][32 * i + arow][akq + 0] = make_float2(va[i].x, va[i].x);
                a_s[nb][32 * i + arow][akq + 1] = make_float2(va[i].y, va[i].y);
                a_s[nb][32 * i + arow][akq + 2] = make_float2(va[i].z, va[i].z);
                a_s[nb][32 * i + arow][akq + 3] = make_float2(va[i].w, va[i].w);
                *reinterpret_cast<float4*>(
                    oA + (size_t)(32 * i) * HH + (size_t)(c + 1) * BK) =
                    make_float4(h16(va[i].x), h16(va[i].y), h16(va[i].z), h16(va[i].w));
            }
#pragma unroll
            for (int j = 0; j < 2; j++)
                *reinterpret_cast<float4*>(&b_s[nb][br0 + 8 * j][bc]) = vb[j];
            __syncthreads();
        }
    }

    // epilogue: +b1, relu, dot w2, reduce over 8 tx lanes
    const float4 b1a = *reinterpret_cast<const float4*>(b1 + tx * 8);
    const float4 b1b = *reinterpret_cast<const float4*>(b1 + tx * 8 + 4);
    const float4 w2a = *reinterpret_cast<const float4*>(w2 + tx * 8);
    const float4 w2b = *reinterpret_cast<const float4*>(w2 + tx * 8 + 4);
    const float b2v = b2[0];
    const float b1v[8] = {b1a.x, b1a.y, b1a.z, b1a.w, b1b.x, b1b.y, b1b.z, b1b.w};
    const float w2v[8] = {w2a.x, w2a.y, w2a.z, w2a.w, w2b.x, w2b.y, w2b.z, w2b.w};

#pragma unroll
    for (int t = 0; t < 8; t++) {
        float p = 0.f;
#pragma unroll
        for (int i = 0; i < 4; i++) {
            float lo = __uint_as_float((unsigned)(acc[t][i] & 0xffffffffull));
            float hi = __uint_as_float((unsigned)(acc[t][i] >> 32));
            p += fmaxf(lo + b1v[2 * i],     0.f) * w2v[2 * i]
               + fmaxf(hi + b1v[2 * i + 1], 0.f) * w2v[2 * i + 1];
        }
        p += __shfl_down_sync(0xffffffffu, p, 4, 8);
        p += __shfl_down_sync(0xffffffffu, p, 2, 8);
        p += __shfl_down_sync(0xffffffffu, p, 1, 8);
        if (tx == 0) d_logits[tok0 + ty + 16 * t] = p + b2v;
    }
}

// ============================================================================
// Kernel 2: per-batch gumbel top-k (full bitonic sort, matches jax.lax.top_k
// descending order + stable lowest-index tiebreak) + logsumexp + log_prob.
// ============================================================================
__global__ __launch_bounds__(512)
void k_topk(const float* __restrict__ noise, float* __restrict__ out,
            int write_extras)
{
    const int b   = blockIdx.x;
    const int tid = threadIdx.x;
    __shared__ ull   keys[SS];
    __shared__ float red[512];

    const float* lg = d_logits + b * SS;
    const float* nu = noise    + b * SS;

    float m = -3.4e38f;
    for (int i = tid; i < SS; i += 512) {
        float l = lg[i];
        float s = l - logf(-logf(nu[i]));          // logit + gumbel
        unsigned u = __float_as_uint(s);
        u = (u & 0x80000000u) ? ~u : (u | 0x80000000u);
        keys[i] = ((ull)u << 32) | (unsigned)(~(unsigned)i);
        m = fmaxf(m, l);
    }
    red[tid] = m; __syncthreads();
    for (int s2 = 256; s2 > 0; s2 >>= 1) {
        if (tid < s2) red[tid] = fmaxf(red[tid], red[tid + s2]);
        __syncthreads();
    }
    m = red[0]; __syncthreads();
    float sum = 0.f;
    for (int i = tid; i < SS; i += 512) sum += expf(lg[i] - m);
    red[tid] = sum; __syncthreads();
    for (int s2 = 256; s2 > 0; s2 >>= 1) {
        if (tid < s2) red[tid] += red[tid + s2];
        __syncthreads();
    }
    const float lse = m + logf(red[0]);
    __syncthreads();

    for (int size = 2; size <= SS; size <<= 1) {
        for (int stride = size >> 1; stride > 0; stride >>= 1) {
            for (int t = tid; t < SS / 2; t += 512) {
                int i = 2 * t - (t & (stride - 1));
                int j = i + stride;
                bool desc = ((i & size) == 0);
                ull a = keys[i], c = keys[j];
                bool sw = desc ? (a < c) : (a > c);
                if (sw) { keys[i] = c; keys[j] = a; }
            }
            __syncthreads();
        }
    }

    float lp = 0.f;
    for (int kk = tid; kk < KSEL; kk += 512) {
        int idx = (int)(~(unsigned)(keys[kk] & 0xffffffffull));
        d_sel[b * KSEL + kk] = idx;
        lp += lg[idx] - lse;
        if (write_extras) {
            out[(size_t)BB * SS * HH + b * KSEL + kk] = (float)idx;           // indices
            out[(size_t)BB * SS * HH + BB * KSEL + b * KSEL + kk] = 1.0f;     // types
        }
    }
    red[tid] = lp; __syncthreads();
    for (int s2 = 256; s2 > 0; s2 >>= 1) {
        if (tid < s2) red[tid] += red[tid + s2];
        __syncthreads();
    }
    if (tid == 0 && write_extras)
        out[(size_t)BB * SS * HH + 2 * BB * KSEL + b] = red[0] / (float)KSEL; // log_prob
}

// ============================================================================
// Kernel 3: zero selected rows (perturb value = TYPE_VALUES[1]*SCALE = 0.0)
// ============================================================================
__global__ __launch_bounds__(256)
void k_zero(float* __restrict__ out)
{
    const int b   = blockIdx.y;
    const int row = d_sel[b * KSEL + blockIdx.x];
    float4* p = reinterpret_cast<float4*>(out + ((size_t)b * SS + row) * HH);
    const float4 z = make_float4(0.f, 0.f, 0.f, 0.f);
    p[threadIdx.x]       = z;
    p[threadIdx.x + 256] = z;
}

// ============================================================================
extern "C" void kernel_launch(void* const* d_in, const int* in_sizes, int n_in,
                              void* d_out, int out_size)
{
    const float* hs = (const float*)d_in[0];   // (8,4096,2048) fp32
    const float* nu = (const float*)d_in[1];   // (8,4096)      fp32
    const float* w1 = (const float*)d_in[2];   // (2048,64)
    const float* b1 = (const float*)d_in[3];   // (64,)
    const float* w2 = (const float*)d_in[4];   // (64,1)
    const float* b2 = (const float*)d_in[5];   // (1,)
    float* out = (float*)d_out;

    const long long need = (long long)BB * SS * HH + 2LL * BB * KSEL + BB;
    const int write_extras = ((long long)out_size >= need) ? 1 : 0;

    k_gemm<<<(BB * SS) / BM, 128>>>(hs, w1, b1, w2, b2, out);
    k_topk<<<BB, 512>>>(nu, out, write_extras);
    k_zero<<<dim3(KSEL, BB), 256>>>(out);
    (void)in_sizes; (void)n_in;
}

// round 8
// speedup vs baseline: 2.5268x; 1.1085x over previous
#include <cuda_runtime.h>
#include <cuda_fp16.h>

#define BB    8
#define SS    4096
#define HH    2048
#define DHH   64
#define KSEL  256

typedef unsigned long long ull;

// scratch (no cudaMalloc allowed)
__device__ float d_logits[BB * SS];
__device__ int   d_sel[BB * KSEL];

__device__ __forceinline__ void fma2(ull& c, ull a, ull b) {
    asm("fma.rn.f32x2 %0, %1, %2, %0;" : "+l"(c) : "l"(a), "l"(b));
}
__device__ __forceinline__ ull mk64(unsigned lo, unsigned hi) {
    ull r; asm("mov.b64 %0, {%1, %2};" : "=l"(r) : "r"(lo), "r"(hi)); return r;
}
__device__ __forceinline__ ull dup64(float a) {
    ull r; asm("mov.b64 %0, {%1, %1};" : "=l"(r) : "f"(a)); return r;
}
// fp32 rounded through fp16 (reference does .astype(float16); harness compares fp32)
__device__ __forceinline__ float h16(float v) {
    return __half2float(__float2half_rn(v));
}

// ============================================================================
// Kernel 1: fused logits GEMM. 8 tok x 8 col per thread; A kept NON-duplicated
// in smem (LDS.32 + ALU mov.b64{r,r} pack) to halve crossbar lane-bytes:
// per warp-kk: A 1KB + B 1KB = 16 SM-cyc, tied with the 32-FFMA2 fma cost.
// Double-buffered single-sync pipeline + fp16-rounded fp32 copy of hs to out.
// ============================================================================
constexpr int BM = 128, BK = 16, NCHUNK = HH / BK;
constexpr int APAD = BK + 4;   // 20-float stride: float4-aligned, bank-spread

__global__ __launch_bounds__(128, 3)
void k_gemm(const float* __restrict__ hs, const float* __restrict__ w1,
            const float* __restrict__ b1, const float* __restrict__ w2,
            const float* __restrict__ b2, float* __restrict__ out)
{
    __shared__ float a_s[2][BM][APAD];   // 20.5KB, non-duplicated
    __shared__ float b_s[2][BK][DHH];    // 8KB

    const int tid  = threadIdx.x;
    const int tx   = tid & 7;
    const int ty   = tid >> 3;               // 0..15
    const int tok0 = blockIdx.x * BM;

    // A staging: flat = i*128 + tid (i=0..3): row = 32*i + (tid>>2), kq=(tid&3)*4
    const int arow = tid >> 2;                // 0..31 (+32i)
    const int akq  = (tid & 3) * 4;           // 0,4,8,12
    // B staging: flat = j*128 + tid (j=0..1): brow = flat>>4, bcol=(flat&15)*4
    const int br0  = tid >> 4;                // 0..7 (j=0), +8 (j=1)
    const int bc   = (tid & 15) * 4;

    const float* hsA = hs  + (size_t)(tok0 + arow) * HH + akq;
    float*       oA  = out + (size_t)(tok0 + arow) * HH + akq;

    ull acc[8][4];
#pragma unroll
    for (int t = 0; t < 8; t++)
#pragma unroll
        for (int i = 0; i < 4; i++) acc[t][i] = 0ull;

    float4 va[4], vb[2];
    // ---- prologue: chunk 0 ----
#pragma unroll
    for (int i = 0; i < 4; i++)
        va[i] = *reinterpret_cast<const float4*>(hsA + (size_t)(32 * i) * HH);
#pragma unroll
    for (int j = 0; j < 2; j++)
        vb[j] = *reinterpret_cast<const float4*>(w1 + (size_t)(br0 + 8 * j) * DHH + bc);
#pragma unroll
    for (int i = 0; i < 4; i++) {
        *reinterpret_cast<float4*>(&a_s[0][32 * i + arow][akq]) = va[i];
        *reinterpret_cast<float4*>(oA + (size_t)(32 * i) * HH) =
            make_float4(h16(va[i].x), h16(va[i].y), h16(va[i].z), h16(va[i].w));
    }
#pragma unroll
    for (int j = 0; j < 2; j++)
        *reinterpret_cast<float4*>(&b_s[0][br0 + 8 * j][bc]) = vb[j];
    __syncthreads();

    for (int c = 0; c < NCHUNK; c++) {
        const int buf = c & 1;

        // prefetch chunk c+1 into registers (overlaps compute below)
        if (c + 1 < NCHUNK) {
#pragma unroll
            for (int i = 0; i < 4; i++)
                va[i] = *reinterpret_cast<const float4*>(
                    hsA + (size_t)(32 * i) * HH + (size_t)(c + 1) * BK);
#pragma unroll
            for (int j = 0; j < 2; j++)
                vb[j] = *reinterpret_cast<const float4*>(
                    w1 + (size_t)((c + 1) * BK + br0 + 8 * j) * DHH + bc);
        }

        // compute chunk c from smem[buf]
#pragma unroll
        for (int kk = 0; kk < BK; kk++) {
            const uint4 u0 = *reinterpret_cast<const uint4*>(&b_s[buf][kk][tx * 8]);
            const uint4 u1 = *reinterpret_cast<const uint4*>(&b_s[buf][kk][tx * 8 + 4]);
            const ull bv0 = mk64(u0.x, u0.y), bv1 = mk64(u0.z, u0.w);
            const ull bv2 = mk64(u1.x, u1.y), bv3 = mk64(u1.z, u1.w);
#pragma unroll
            for (int t = 0; t < 8; t++) {
                const ull av = dup64(a_s[buf][ty + 16 * t][kk]);
                fma2(acc[t][0], av, bv0);
                fma2(acc[t][1], av, bv1);
                fma2(acc[t][2], av, bv2);
                fma2(acc[t][3], av, bv3);
            }
        }

        // stage chunk c+1 into the other buffer; emit output copy
        if (c + 1 < NCHUNK) {
            const int nb = buf ^ 1;
#pragma unroll
            for (int i = 0; i < 4; i++) {
                *reinterpret_cast<float4*>(&a_s[nb][32 * i + arow][akq]) = va[i];
                *reinterpret_cast<float4*>(
                    oA + (size_t)(32 * i) * HH + (size_t)(c + 1) * BK) =
                    make_float4(h16(va[i].x), h16(va[i].y), h16(va[i].z), h16(va[i].w));
            }
#pragma unroll
            for (int j = 0; j < 2; j++)
                *reinterpret_cast<float4*>(&b_s[nb][br0 + 8 * j][bc]) = vb[j];
            __syncthreads();
        }
    }

    // epilogue: +b1, relu, dot w2, reduce over 8 tx lanes
    const float4 b1a = *reinterpret_cast<const float4*>(b1 + tx * 8);
    const float4 b1b = *reinterpret_cast<const float4*>(b1 + tx * 8 + 4);
    const float4 w2a = *reinterpret_cast<const float4*>(w2 + tx * 8);
    const float4 w2b = *reinterpret_cast<const float4*>(w2 + tx * 8 + 4);
    const float b2v = b2[0];
    const float b1v[8] = {b1a.x, b1a.y, b1a.z, b1a.w, b1b.x, b1b.y, b1b.z, b1b.w};
    const float w2v[8] = {w2a.x, w2a.y, w2a.z, w2a.w, w2b.x, w2b.y, w2b.z, w2b.w};

#pragma unroll
    for (int t = 0; t < 8; t++) {
        float p = 0.f;
#pragma unroll
        for (int i = 0; i < 4; i++) {
            float lo = __uint_as_float((unsigned)(acc[t][i] & 0xffffffffull));
            float hi = __uint_as_float((unsigned)(acc[t][i] >> 32));
            p += fmaxf(lo + b1v[2 * i],     0.f) * w2v[2 * i]
               + fmaxf(hi + b1v[2 * i + 1], 0.f) * w2v[2 * i + 1];
        }
        p += __shfl_down_sync(0xffffffffu, p, 4, 8);
        p += __shfl_down_sync(0xffffffffu, p, 2, 8);
        p += __shfl_down_sync(0xffffffffu, p, 1, 8);
        if (tx == 0) d_logits[tok0 + ty + 16 * t] = p + b2v;
    }
}

// ============================================================================
// Kernel 2: per-batch gumbel top-k (full bitonic sort, matches jax.lax.top_k
// descending order + stable lowest-index tiebreak) + logsumexp + log_prob.
// ============================================================================
__global__ __launch_bounds__(512)
void k_topk(const float* __restrict__ noise, float* __restrict__ out,
            int write_extras)
{
    const int b   = blockIdx.x;
    const int tid = threadIdx.x;
    __shared__ ull   keys[SS];
    __shared__ float red[512];

    const float* lg = d_logits + b * SS;
    const float* nu = noise    + b * SS;

    float m = -3.4e38f;
    for (int i = tid; i < SS; i += 512) {
        float l = lg[i];
        float s = l - logf(-logf(nu[i]));          // logit + gumbel
        unsigned u = __float_as_uint(s);
        u = (u & 0x80000000u) ? ~u : (u | 0x80000000u);
        keys[i] = ((ull)u << 32) | (unsigned)(~(unsigned)i);
        m = fmaxf(m, l);
    }
    red[tid] = m; __syncthreads();
    for (int s2 = 256; s2 > 0; s2 >>= 1) {
        if (tid < s2) red[tid] = fmaxf(red[tid], red[tid + s2]);
        __syncthreads();
    }
    m = red[0]; __syncthreads();
    float sum = 0.f;
    for (int i = tid; i < SS; i += 512) sum += expf(lg[i] - m);
    red[tid] = sum; __syncthreads();
    for (int s2 = 256; s2 > 0; s2 >>= 1) {
        if (tid < s2) red[tid] += red[tid + s2];
        __syncthreads();
    }
    const float lse = m + logf(red[0]);
    __syncthreads();

    for (int size = 2; size <= SS; size <<= 1) {
        for (int stride = size >> 1; stride > 0; stride >>= 1) {
            for (int t = tid; t < SS / 2; t += 512) {
                int i = 2 * t - (t & (stride - 1));
                int j = i + stride;
                bool desc = ((i & size) == 0);
                ull a = keys[i], c = keys[j];
                bool sw = desc ? (a < c) : (a > c);
                if (sw) { keys[i] = c; keys[j] = a; }
            }
            __syncthreads();
        }
    }

    float lp = 0.f;
    for (int kk = tid; kk < KSEL; kk += 512) {
        int idx = (int)(~(unsigned)(keys[kk] & 0xffffffffull));
        d_sel[b * KSEL + kk] = idx;
        lp += lg[idx] - lse;
        if (write_extras) {
            out[(size_t)BB * SS * HH + b * KSEL + kk] = (float)idx;           // indices
            out[(size_t)BB * SS * HH + BB * KSEL + b * KSEL + kk] = 1.0f;     // types
        }
    }
    red[tid] = lp; __syncthreads();
    for (int s2 = 256; s2 > 0; s2 >>= 1) {
        if (tid < s2) red[tid] += red[tid + s2];
        __syncthreads();
    }
    if (tid == 0 && write_extras)
        out[(size_t)BB * SS * HH + 2 * BB * KSEL + b] = red[0] / (float)KSEL; // log_prob
}

// ============================================================================
// Kernel 3: zero selected rows (perturb value = TYPE_VALUES[1]*SCALE = 0.0)
// ============================================================================
__global__ __launch_bounds__(256)
void k_zero(float* __restrict__ out)
{
    const int b   = blockIdx.y;
    const int row = d_sel[b * KSEL + blockIdx.x];
    float4* p = reinterpret_cast<float4*>(out + ((size_t)b * SS + row) * HH);
    const float4 z = make_float4(0.f, 0.f, 0.f, 0.f);
    p[threadIdx.x]       = z;
    p[threadIdx.x + 256] = z;
}

// ============================================================================
extern "C" void kernel_launch(void* const* d_in, const int* in_sizes, int n_in,
                              void* d_out, int out_size)
{
    const float* hs = (const float*)d_in[0];   // (8,4096,2048) fp32
    const float* nu = (const float*)d_in[1];   // (8,4096)      fp32
    const float* w1 = (const float*)d_in[2];   // (2048,64)
    const float* b1 = (const float*)d_in[3];   // (64,)
    const float* w2 = (const float*)d_in[4];   // (64,1)
    const float* b2 = (const float*)d_in[5];   // (1,)
    float* out = (float*)d_out;

    const long long need = (long long)BB * SS * HH + 2LL * BB * KSEL + BB;
    const int write_extras = ((long long)out_size >= need) ? 1 : 0;

    k_gemm<<<(BB * SS) / BM, 128>>>(hs, w1, b1, w2, b2, out);
    k_topk<<<BB, 512>>>(nu, out, write_extras);
    k_zero<<<dim3(KSEL, BB), 256>>>(out);
    (void)in_sizes; (void)n_in;
}